// round 12
// baseline (speedup 1.0000x reference)
#include <cuda_runtime.h>
#include <math.h>

#define W_IMG 4096
// float(pi) - pi  (cos(pi_f) == -1 exactly, sin(pi_f) == -DPI)
#define DPI 8.742278e-8f
#define ZMIN 1e-12f

__device__ __forceinline__ float rcpa(float x){ float y; asm("rcp.approx.f32 %0, %1;" : "=f"(y) : "f"(x)); return y; }
__device__ __forceinline__ float rsqa(float x){ float y; asm("rsqrt.approx.f32 %0, %1;" : "=f"(y) : "f"(x)); return y; }
// y with sign flipped by sign bit of x: single LOP3
__device__ __forceinline__ float xsign(float y, float x){
    return __int_as_float(__float_as_int(y) ^ (__float_as_int(x) & 0x80000000u));
}
// a - b as FFMA-imm (exact)
__device__ __forceinline__ float fsub(float a, float b){ return fmaf(b, -1.f, a); }
// float-domain ordered compares: 1.0f / 0.0f, false on NaN
__device__ __forceinline__ float fsetgt(float a, float b){
    float d; asm("set.gt.f32.f32 %0, %1, %2;" : "=f"(d) : "f"(a), "f"(b)); return d;
}
__device__ __forceinline__ float fsetne(float a, float b){
    float d; asm("set.ne.f32.f32 %0, %1, %2;" : "=f"(d) : "f"(a), "f"(b)); return d;
}

// ---------- robust sin/cos of atan(num/den): handles inf operands too -------
__device__ __forceinline__ void cs_atan_core(float num, float den, float& sa, float& ca) {
    float an = fabsf(num), ad = fabsf(den);
    bool sw = an > ad;
    float top = sw ? den : num;
    float bot = sw ? num : den;
    float q  = top * rcpa(bot);                 // |q| <= 1, or NaN
    float rr = rsqa(fmaf(q, q, 1.f));
    float sg = copysignf(1.f, num) * copysignf(1.f, den);
    ca = sw ? fabsf(q) * rr : rr;
    sa = sw ? sg * rr : q * rr;
}

// ---------- per-neighbor raw: nzn = coef*(M*R) + t ----------
__device__ __forceinline__ void neigh_raw(float coef, float M, float R, float t,
                                          float nt2, float& rn, float& v) {
    float nzn = fmaf(coef, M * R, t);
    rn = rsqa(fmaf(nzn, nzn, nt2));
    v  = -(nzn * rn);
}

// ---------- HOT pixel: all inputs finite positive depths (z > ZMIN) ----------
__device__ __forceinline__ float3 hot_pixel(
    float zc, float fuc,
    float DmM, float DmP,                 // 1/z left, right
    float zmM, float zmP,                 // z left, right
    float XmC, float XmM, float XmP,      // X center/left/right
    float zu, float zdn, float Du, float Dd_,  // z and 1/z up, down
    float fv0, float fvm, float fvp,
    float fx, float fy, int sf)
{
    float nx_t = fsub(DmP, DmM) * fx;
    float ny_t = fsub(Dd_, Du) * fy;
    float nt2 = fmaf(nx_t, nx_t, ny_t * ny_t);

    float pt = ny_t * fv0;                  // shared by left/right
    float gt = nx_t * fuc;                  // shared by up/down
    float Yc = zc * fv0;

    float Zu  = fsub(zc, zu),  Zdn = fsub(zc, zdn);
    float Zl  = fsub(zc, zmM), Zr  = fsub(zc, zmP);
    float Ru  = rcpa(Zu), Rd = rcpa(Zdn), Rl = rcpa(Zl), Rr = rcpa(Zr);
    float Yu  = fmaf(zu,  -fvm, Yc);
    float Ydn = fmaf(zdn, -fvp, Yc);
    float Xl  = fsub(XmC, XmM), Xr = fsub(XmC, XmP);

    float rn0, v0, rn1, v1, rn2, v2, rn3, v3;
    neigh_raw(ny_t, Yu,  Ru, gt, nt2, rn0, v0);   // up
    neigh_raw(nx_t, Xl,  Rl, pt, nt2, rn1, v1);   // left
    neigh_raw(nx_t, Xr,  Rr, pt, nt2, rn2, v2);   // right
    neigh_raw(ny_t, Ydn, Rd, gt, nt2, rn3, v3);   // down

    float srn, snz;
    if (sf) {
        // signed count: sg_i = sign(v_i) as +-1.0 (0 for zero/NaN; ordered ne)
        float sg0 = xsign(fsetne(v0, 0.f), v0);
        float sg1 = xsign(fsetne(v1, 0.f), v1);
        float sg2 = xsign(fsetne(v2, 0.f), v2);
        float sg3 = xsign(fsetne(v3, 0.f), v3);
        float ssum = fmaf(sg3, 1.f, fmaf(sg2, 1.f, fmaf(sg1, 1.f, sg0)));
        // majority side = sign bit of ssum; w_i > 0 <=> kept
        float w0 = xsign(v0, ssum), w1 = xsign(v1, ssum);
        float w2 = xsign(v2, ssum), w3 = xsign(v3, ssum);
        // FMNMX absorbs NaN (fmaxf(NaN,0)=0)
        float m0 = fmaxf(w0, 0.f), m1 = fmaxf(w1, 0.f);
        float m2 = fmaxf(w2, 0.f), m3 = fmaxf(w3, 0.f);
        float msum = fmaf(m3, 1.f, fmaf(m2, 1.f, fmaf(m1, 1.f, m0)));
        snz = xsign(msum, ssum);
        float f0 = fsetgt(w0, 0.f), f1 = fsetgt(w1, 0.f);
        float f2 = fsetgt(w2, 0.f), f3 = fsetgt(w3, 0.f);
        float rc0 = fmaxf(rn0, 0.f), rc1 = fmaxf(rn1, 0.f);
        float rc2 = fmaxf(rn2, 0.f), rc3 = fmaxf(rn3, 0.f);
        srn = fmaf(f3, rc3, fmaf(f2, rc2, fmaf(f1, rc1, f0 * rc0)));
    } else {
        float cv0 = (v0 != v0) ? 0.f : v0, cr0 = (v0 != v0) ? 0.f : rn0;
        float cv1 = (v1 != v1) ? 0.f : v1, cr1 = (v1 != v1) ? 0.f : rn1;
        float cv2 = (v2 != v2) ? 0.f : v2, cr2 = (v2 != v2) ? 0.f : rn2;
        float cv3 = (v3 != v3) ? 0.f : v3, cr3 = (v3 != v3) ? 0.f : rn3;
        srn = fmaf(cr3, 1.f, fmaf(cr2, 1.f, fmaf(cr1, 1.f, cr0)));
        snz = fmaf(cv3, 1.f, fmaf(cv2, 1.f, fmaf(cv1, 1.f, cv0)));
    }

    // Collapsed reconstruction: output = sign(snz) * srn * rr * (nxr, nyr),
    // nz = |snz| * rr, where rr = rsqrt(snz^2 + srn^2*nt2). The DPI rotation
    // of the reference survives exactly in (nxr, nyr); signs match the
    // reference bit-for-bit, magnitudes to ~1e-7.
    float nxr = fmaf(-DPI, ny_t, nx_t);
    float nyr = fmaf(DPI, nx_t, ny_t);
    float num2 = (srn * srn) * nt2;
    float rr  = rsqa(fmaf(snz, snz, num2));
    float k   = xsign(srn * rr, snz);
    float nx = k * nxr;
    float ny = k * nyr;
    float nz = fabsf(snz) * rr;
    if (nz != nz) { nx = 0.f; ny = 0.f; nz = -1.f; }
    float s = (ny > 0.f) ? -1.f : 1.f;
    return make_float3(nx * s, ny * s, nz * s);
}

// ---------- generic finisher (robust to inf nx_t/ny_t) ----------------------
__device__ __forceinline__ void gen_finish(
    float nx_t, float ny_t,
    const float* Xd, const float* Yd, const float* Zd,
    int sf, float& onx, float& ony, float& onz)
{
    float sa, ca; cs_atan_core(ny_t, nx_t, sa, ca);
    float a = fmaf(sa, DPI, -ca);
    float b = -fmaf(ca, DPI, sa);
    float nt2 = fmaf(nx_t, nx_t, ny_t * ny_t);

    float nxv[4], nyv[4], nzv[4];
#pragma unroll
    for (int i = 0; i < 4; i++) {
        float nz_i = -fmaf(nx_t, Xd[i], ny_t * Yd[i]) * rcpa(Zd[i]);
        float rn = rsqa(fmaf(nz_i, nz_i, nt2));
        float vx = nx_t * rn, vy = ny_t * rn, vz = nz_i * rn;
        nxv[i] = (vx != vx) ? 0.f : vx;
        nyv[i] = (vy != vy) ? 0.f : vy;
        nzv[i] = (vz != vz) ? 0.f : vz;
    }
    if (sf) {
        int np = 0, nn = 0;
#pragma unroll
        for (int i = 0; i < 4; i++) { np += nzv[i] > 0.f; nn += nzv[i] < 0.f; }
        bool ps = np >= nn;
#pragma unroll
        for (int i = 0; i < 4; i++) {
            float fm = (ps ? (nzv[i] > 0.f) : (nzv[i] < 0.f)) ? 1.f : 0.f;
            nxv[i] *= fm; nyv[i] *= fm; nzv[i] *= fm;
        }
    }
    float snx = (nxv[0] + nxv[1]) + (nxv[2] + nxv[3]);
    float sny = (nyv[0] + nyv[1]) + (nyv[2] + nyv[3]);
    float snz = (nzv[0] + nzv[1]) + (nzv[2] + nzv[3]);

    float num = fmaf(snx, a, sny * b);
    float st, ct; cs_atan_core(num, snz, st, ct);
    float nx = st * a, ny = st * b, nz = ct;
    if (nz != nz) { nx = 0.f; ny = 0.f; nz = -1.f; }
    float s = (ny > 0.f) ? -1.f : 1.f;
    onx = nx * s; ony = ny * s; onz = nz * s;
}

__device__ __noinline__ void generic_pixel(const float* __restrict__ depth,
    int r, int c, int h, int w, float fx, float fy, float ifx,
    float cx, float cy, int sf, float& onx, float& ony, float& onz)
{
    const int dy[5] = {0, -1, 0, 0, 1};
    const int dx[5] = {0,  0,-1, 1, 0};
    float Xs[5], Ys[5], Zs[5], Ds[5];
#pragma unroll
    for (int i = 0; i < 5; i++) {
        int rr_ = r + dy[i], cc = c + dx[i];
        bool inb = (rr_ >= 0) & (rr_ < h) & (cc >= 0) & (cc < w);
        float X = 0.f, Y = 0.f, Z = 0.f, D = 0.f;
        if (inb) {
            float z = depth[rr_ * w + cc];
            Z = z;
            Y = z * ((float)rr_ - cy) * ifx;   // reference uses fx for Y too
            X = z * ((float)cc - cx) * ifx;
            if (Y <= 0.f) { Z = 0.f; Y = 0.f; } // X intentionally NOT zeroed
            if (Z != Z) Z = 0.f;
            D = rcpa(Z);                         // inf where Z == 0
        }
        Xs[i] = X; Ys[i] = Y; Zs[i] = Z; Ds[i] = D;
    }
    float nx_t = (Ds[3] - Ds[2]) * fx;
    float ny_t = (Ds[4] - Ds[1]) * fy;
    float Xd[4], Yd[4], Zd[4];
#pragma unroll
    for (int i = 0; i < 4; i++) {
        Xd[i] = Xs[0] - Xs[i + 1];
        Yd[i] = Ys[0] - Ys[i + 1];
        Zd[i] = Zs[0] - Zs[i + 1];
    }
    gen_finish(nx_t, ny_t, Xd, Yd, Zd, sf, onx, ony, onz);
}

__global__ __launch_bounds__(128, 10)
void nim_kernel(const float* __restrict__ depth,
                const float* __restrict__ cam,
                const int*   __restrict__ sf_ptr,
                float* __restrict__ out,
                int h, int w)
{
    int r  = blockIdx.y * 4 + threadIdx.y;
    int c0 = (blockIdx.x * 32 + threadIdx.x) * 4;
    if (r >= h || c0 + 3 >= w) return;

    float fx = cam[0], fy = cam[4], cx = cam[2], cy = cam[5];
    float ifx = 1.0f / fx;
    int sf = sf_ptr[0];
    int hw = h * w;
    int base = r * w + c0;

    bool interior = (r >= 1) & (r < h - 1) & (c0 >= 4) & (c0 <= w - 8);

    if (interior) {
        float4 zu4 = *(const float4*)(depth + base - w);
        float4 zd4 = *(const float4*)(depth + base + w);
        float4 zm4 = *(const float4*)(depth + base);
        float  zm0 = depth[base - 1];
        float  zm5 = depth[base + 4];

        float zu0 = zu4.x, zu1 = zu4.y, zu2 = zu4.z, zu3 = zu4.w;
        float zd0 = zd4.x, zd1 = zd4.y, zd2 = zd4.z, zd3 = zd4.w;
        float zm1 = zm4.x, zm2 = zm4.y, zm3 = zm4.z, zm4v = zm4.w;

        float fv0 = ((float)r       - cy) * ifx;
        float fvm = ((float)(r - 1) - cy) * ifx;
        float fvp = ((float)(r + 1) - cy) * ifx;

        // min-tree positivity check (13 FMNMX + 1 compare instead of 14
        // compares + AND-reduce). fminf drops NaN operands; a NaN depth thus
        // enters the hot path, where it poisons exactly the affected pixel's
        // gradient/Zd chain -> all 4 neighbors excluded -> snz=+-0, srn=0 ->
        // nz=0*inf=NaN -> fixup (0,0,-1), matching the reference's NaN
        // cascade for that pixel. Negative/zero depths still fail min>ZMIN.
        float mnU = fminf(fminf(zu0, zu1), fminf(zu2, zu3));
        float mnD = fminf(fminf(zd0, zd1), fminf(zd2, zd3));
        float mnM = fminf(fminf(fminf(zm0, zm1), fminf(zm2, zm3)), fminf(zm4v, zm5));
        bool allpos = fminf(mnU, fminf(mnD, mnM)) > ZMIN;

        if (allpos && fvp <= 0.f) {
            // Whole neighborhood masked (Y<=0 -> Z=0 -> D=inf) -> NaN cascade
            // -> reference emits exactly (0, 0, -1).
            float4 zro = make_float4(0.f, 0.f, 0.f, 0.f);
            float4 neg = make_float4(-1.f, -1.f, -1.f, -1.f);
            *(float4*)(out + base)          = zro;
            *(float4*)(out + base + hw)     = zro;
            *(float4*)(out + base + 2 * hw) = neg;
            return;
        }

        if (allpos && fvm > 0.f) {
            float fu0 = ((float)(c0 - 1) - cx) * ifx;
            float fu1 = fmaf(ifx, 1.f, fu0);
            float fu2 = fmaf(ifx, 1.f, fu1);
            float fu3 = fmaf(ifx, 1.f, fu2);
            float fu4 = fmaf(ifx, 1.f, fu3);
            float fu5 = fmaf(ifx, 1.f, fu4);

            float Dm0 = rcpa(zm0), Dm1 = rcpa(zm1), Dm2 = rcpa(zm2);
            float Dm3 = rcpa(zm3), Dm4 = rcpa(zm4v), Dm5 = rcpa(zm5);
            float Du0 = rcpa(zu0), Du1 = rcpa(zu1), Du2 = rcpa(zu2), Du3 = rcpa(zu3);
            float Dd0 = rcpa(zd0), Dd1 = rcpa(zd1), Dd2 = rcpa(zd2), Dd3 = rcpa(zd3);

            float Xm0 = zm0 * fu0, Xm1 = zm1 * fu1, Xm2 = zm2 * fu2;
            float Xm3 = zm3 * fu3, Xm4 = zm4v * fu4, Xm5 = zm5 * fu5;

            float3 o0 = hot_pixel(zm1,  fu1, Dm0, Dm2, zm0, zm2, Xm1, Xm0, Xm2,
                                  zu0, zd0, Du0, Dd0, fv0, fvm, fvp, fx, fy, sf);
            float3 o1 = hot_pixel(zm2,  fu2, Dm1, Dm3, zm1, zm3, Xm2, Xm1, Xm3,
                                  zu1, zd1, Du1, Dd1, fv0, fvm, fvp, fx, fy, sf);
            float3 o2 = hot_pixel(zm3,  fu3, Dm2, Dm4, zm2, zm4v, Xm3, Xm2, Xm4,
                                  zu2, zd2, Du2, Dd2, fv0, fvm, fvp, fx, fy, sf);
            float3 o3 = hot_pixel(zm4v, fu4, Dm3, Dm5, zm3, zm5, Xm4, Xm3, Xm5,
                                  zu3, zd3, Du3, Dd3, fv0, fvm, fvp, fx, fy, sf);

            *(float4*)(out + base)          = make_float4(o0.x, o1.x, o2.x, o3.x);
            *(float4*)(out + base + hw)     = make_float4(o0.y, o1.y, o2.y, o3.y);
            *(float4*)(out + base + 2 * hw) = make_float4(o0.z, o1.z, o2.z, o3.z);
            return;
        }
    }

    // Borders, horizon band, pathological depth values.
    for (int p = 0; p < 4; p++) {
        float onx, ony, onz;
        generic_pixel(depth, r, c0 + p, h, w, fx, fy, ifx, cx, cy, sf, onx, ony, onz);
        out[base + p]          = onx;
        out[base + p + hw]     = ony;
        out[base + p + 2 * hw] = onz;
    }
}

extern "C" void kernel_launch(void* const* d_in, const int* in_sizes, int n_in,
                              void* d_out, int out_size) {
    const float* depth = (const float*)d_in[0];
    const float* cam   = (const float*)d_in[1];
    const int*   sf    = (const int*)d_in[2];
    float* out = (float*)d_out;

    int w = W_IMG;
    int h = in_sizes[0] / w;

    dim3 block(32, 4);
    dim3 grid((w + 127) / 128, (h + 3) / 4);
    nim_kernel<<<grid, block>>>(depth, cam, sf, out, h, w);
}

// round 13
// speedup vs baseline: 1.0562x; 1.0562x over previous
#include <cuda_runtime.h>
#include <math.h>

#define W_IMG 4096
// float(pi) - pi  (cos(pi_f) == -1 exactly, sin(pi_f) == -DPI)
#define DPI 8.742278e-8f
#define ZMIN 1e-12f

__device__ __forceinline__ float rcpa(float x){ float y; asm("rcp.approx.f32 %0, %1;" : "=f"(y) : "f"(x)); return y; }
__device__ __forceinline__ float rsqa(float x){ float y; asm("rsqrt.approx.f32 %0, %1;" : "=f"(y) : "f"(x)); return y; }
// y with sign flipped by sign bit of x: single LOP3
__device__ __forceinline__ float xsign(float y, float x){
    return __int_as_float(__float_as_int(y) ^ (__float_as_int(x) & 0x80000000u));
}
// a - b as FFMA-imm (exact)
__device__ __forceinline__ float fsub(float a, float b){ return fmaf(b, -1.f, a); }
// float-domain ordered compares: 1.0f / 0.0f, false on NaN
__device__ __forceinline__ float fsetgt(float a, float b){
    float d; asm("set.gt.f32.f32 %0, %1, %2;" : "=f"(d) : "f"(a), "f"(b)); return d;
}
__device__ __forceinline__ float fsetne(float a, float b){
    float d; asm("set.ne.f32.f32 %0, %1, %2;" : "=f"(d) : "f"(a), "f"(b)); return d;
}

// ---------- robust sin/cos of atan(num/den): handles inf operands too -------
__device__ __forceinline__ void cs_atan_core(float num, float den, float& sa, float& ca) {
    float an = fabsf(num), ad = fabsf(den);
    bool sw = an > ad;
    float top = sw ? den : num;
    float bot = sw ? num : den;
    float q  = top * rcpa(bot);                 // |q| <= 1, or NaN
    float rr = rsqa(fmaf(q, q, 1.f));
    float sg = copysignf(1.f, num) * copysignf(1.f, den);
    ca = sw ? fabsf(q) * rr : rr;
    sa = sw ? sg * rr : q * rr;
}

// ---------- per-neighbor raw: nzn = coef*(M*R) + t ----------
__device__ __forceinline__ void neigh_raw(float coef, float M, float R, float t,
                                          float nt2, float& rn, float& v) {
    float nzn = fmaf(coef, M * R, t);
    rn = rsqa(fmaf(nzn, nzn, nt2));
    v  = -(nzn * rn);
}
// ---------- horizontal neighbor via precomputed edge ratio E = dX*rcp(dH) ---
__device__ __forceinline__ void neigh_e(float coef, float E, float t,
                                        float nt2, float& rn, float& v) {
    float nzn = fmaf(coef, E, t);
    rn = rsqa(fmaf(nzn, nzn, nt2));
    v  = -(nzn * rn);
}

// ---------- HOT pixel: all inputs finite positive depths (z > ZMIN) ----------
__device__ __forceinline__ float3 hot_pixel(
    float zc, float fuc,
    float DmM, float DmP,                 // 1/z left, right
    float EL, float ER,                   // shared edge ratios dX*rcp(dH)
    float zu, float zdn, float Du, float Dd_,  // z and 1/z up, down
    float fv0, float fvm, float fvp,
    float fx, float fy, int sf)
{
    float nx_t = fsub(DmP, DmM) * fx;
    float ny_t = fsub(Dd_, Du) * fy;
    float nt2 = fmaf(nx_t, nx_t, ny_t * ny_t);

    float pt = ny_t * fv0;                  // shared by left/right
    float gt = nx_t * fuc;                  // shared by up/down
    float Yc = zc * fv0;

    float Zu  = fsub(zc, zu),  Zdn = fsub(zc, zdn);
    float Ru  = rcpa(Zu), Rd = rcpa(Zdn);
    float Yu  = fmaf(zu,  -fvm, Yc);
    float Ydn = fmaf(zdn, -fvp, Yc);

    float rn0, v0, rn1, v1, rn2, v2, rn3, v3;
    neigh_raw(ny_t, Yu,  Ru, gt, nt2, rn0, v0);   // up
    neigh_e  (nx_t, EL,      pt, nt2, rn1, v1);   // left
    neigh_e  (nx_t, ER,      pt, nt2, rn2, v2);   // right
    neigh_raw(ny_t, Ydn, Rd, gt, nt2, rn3, v3);   // down

    float srn, snz;
    if (sf) {
        // signed count: sg_i = sign(v_i) as +-1.0 (0 for zero/NaN; ordered ne)
        float sg0 = xsign(fsetne(v0, 0.f), v0);
        float sg1 = xsign(fsetne(v1, 0.f), v1);
        float sg2 = xsign(fsetne(v2, 0.f), v2);
        float sg3 = xsign(fsetne(v3, 0.f), v3);
        float ssum = fmaf(sg3, 1.f, fmaf(sg2, 1.f, fmaf(sg1, 1.f, sg0)));
        // majority side = sign bit of ssum; w_i > 0 <=> kept
        float w0 = xsign(v0, ssum), w1 = xsign(v1, ssum);
        float w2 = xsign(v2, ssum), w3 = xsign(v3, ssum);
        // FMNMX absorbs NaN (fmaxf(NaN,0)=0)
        float m0 = fmaxf(w0, 0.f), m1 = fmaxf(w1, 0.f);
        float m2 = fmaxf(w2, 0.f), m3 = fmaxf(w3, 0.f);
        float msum = fmaf(m3, 1.f, fmaf(m2, 1.f, fmaf(m1, 1.f, m0)));
        snz = xsign(msum, ssum);
        float f0 = fsetgt(w0, 0.f), f1 = fsetgt(w1, 0.f);
        float f2 = fsetgt(w2, 0.f), f3 = fsetgt(w3, 0.f);
        float rc0 = fmaxf(rn0, 0.f), rc1 = fmaxf(rn1, 0.f);
        float rc2 = fmaxf(rn2, 0.f), rc3 = fmaxf(rn3, 0.f);
        srn = fmaf(f3, rc3, fmaf(f2, rc2, fmaf(f1, rc1, f0 * rc0)));
    } else {
        float cv0 = (v0 != v0) ? 0.f : v0, cr0 = (v0 != v0) ? 0.f : rn0;
        float cv1 = (v1 != v1) ? 0.f : v1, cr1 = (v1 != v1) ? 0.f : rn1;
        float cv2 = (v2 != v2) ? 0.f : v2, cr2 = (v2 != v2) ? 0.f : rn2;
        float cv3 = (v3 != v3) ? 0.f : v3, cr3 = (v3 != v3) ? 0.f : rn3;
        srn = fmaf(cr3, 1.f, fmaf(cr2, 1.f, fmaf(cr1, 1.f, cr0)));
        snz = fmaf(cv3, 1.f, fmaf(cv2, 1.f, fmaf(cv1, 1.f, cv0)));
    }

    // Collapsed reconstruction: output = sign(snz) * srn * rr * (nxr, nyr),
    // nz = |snz| * rr, where rr = rsqrt(snz^2 + srn^2*nt2). The DPI rotation
    // of the reference survives exactly in (nxr, nyr); signs match the
    // reference bit-for-bit, magnitudes to ~1e-7.
    float nxr = fmaf(-DPI, ny_t, nx_t);
    float nyr = fmaf(DPI, nx_t, ny_t);
    float num2 = (srn * srn) * nt2;
    float rr  = rsqa(fmaf(snz, snz, num2));
    float k   = xsign(srn * rr, snz);
    float nx = k * nxr;
    float ny = k * nyr;
    float nz = fabsf(snz) * rr;
    if (nz != nz) { nx = 0.f; ny = 0.f; nz = -1.f; }
    float s = (ny > 0.f) ? -1.f : 1.f;
    return make_float3(nx * s, ny * s, nz * s);
}

// ---------- generic finisher (robust to inf nx_t/ny_t) ----------------------
__device__ __forceinline__ void gen_finish(
    float nx_t, float ny_t,
    const float* Xd, const float* Yd, const float* Zd,
    int sf, float& onx, float& ony, float& onz)
{
    float sa, ca; cs_atan_core(ny_t, nx_t, sa, ca);
    float a = fmaf(sa, DPI, -ca);
    float b = -fmaf(ca, DPI, sa);
    float nt2 = fmaf(nx_t, nx_t, ny_t * ny_t);

    float nxv[4], nyv[4], nzv[4];
#pragma unroll
    for (int i = 0; i < 4; i++) {
        float nz_i = -fmaf(nx_t, Xd[i], ny_t * Yd[i]) * rcpa(Zd[i]);
        float rn = rsqa(fmaf(nz_i, nz_i, nt2));
        float vx = nx_t * rn, vy = ny_t * rn, vz = nz_i * rn;
        nxv[i] = (vx != vx) ? 0.f : vx;
        nyv[i] = (vy != vy) ? 0.f : vy;
        nzv[i] = (vz != vz) ? 0.f : vz;
    }
    if (sf) {
        int np = 0, nn = 0;
#pragma unroll
        for (int i = 0; i < 4; i++) { np += nzv[i] > 0.f; nn += nzv[i] < 0.f; }
        bool ps = np >= nn;
#pragma unroll
        for (int i = 0; i < 4; i++) {
            float fm = (ps ? (nzv[i] > 0.f) : (nzv[i] < 0.f)) ? 1.f : 0.f;
            nxv[i] *= fm; nyv[i] *= fm; nzv[i] *= fm;
        }
    }
    float snx = (nxv[0] + nxv[1]) + (nxv[2] + nxv[3]);
    float sny = (nyv[0] + nyv[1]) + (nyv[2] + nyv[3]);
    float snz = (nzv[0] + nzv[1]) + (nzv[2] + nzv[3]);

    float num = fmaf(snx, a, sny * b);
    float st, ct; cs_atan_core(num, snz, st, ct);
    float nx = st * a, ny = st * b, nz = ct;
    if (nz != nz) { nx = 0.f; ny = 0.f; nz = -1.f; }
    float s = (ny > 0.f) ? -1.f : 1.f;
    onx = nx * s; ony = ny * s; onz = nz * s;
}

__device__ __forceinline__ void generic_pixel(const float* __restrict__ depth,
    int r, int c, int h, int w, float fx, float fy, float ifx,
    float cx, float cy, int sf, float& onx, float& ony, float& onz)
{
    const int dy[5] = {0, -1, 0, 0, 1};
    const int dx[5] = {0,  0,-1, 1, 0};
    float Xs[5], Ys[5], Zs[5], Ds[5];
#pragma unroll
    for (int i = 0; i < 5; i++) {
        int rr_ = r + dy[i], cc = c + dx[i];
        bool inb = (rr_ >= 0) & (rr_ < h) & (cc >= 0) & (cc < w);
        float X = 0.f, Y = 0.f, Z = 0.f, D = 0.f;
        if (inb) {
            float z = depth[rr_ * w + cc];
            Z = z;
            Y = z * ((float)rr_ - cy) * ifx;   // reference uses fx for Y too
            X = z * ((float)cc - cx) * ifx;
            if (Y <= 0.f) { Z = 0.f; Y = 0.f; } // X intentionally NOT zeroed
            if (Z != Z) Z = 0.f;
            D = rcpa(Z);                         // inf where Z == 0
        }
        Xs[i] = X; Ys[i] = Y; Zs[i] = Z; Ds[i] = D;
    }
    float nx_t = (Ds[3] - Ds[2]) * fx;
    float ny_t = (Ds[4] - Ds[1]) * fy;
    float Xd[4], Yd[4], Zd[4];
#pragma unroll
    for (int i = 0; i < 4; i++) {
        Xd[i] = Xs[0] - Xs[i + 1];
        Yd[i] = Ys[0] - Ys[i + 1];
        Zd[i] = Zs[0] - Zs[i + 1];
    }
    gen_finish(nx_t, ny_t, Xd, Yd, Zd, sf, onx, ony, onz);
}

__global__ __launch_bounds__(128, 10)
void nim_kernel(const float* __restrict__ depth,
                const float* __restrict__ cam,
                const int*   __restrict__ sf_ptr,
                float* __restrict__ out,
                int h, int w)
{
    int r  = blockIdx.y * 4 + threadIdx.y;
    int c0 = (blockIdx.x * 32 + threadIdx.x) * 4;
    if (r >= h || c0 + 3 >= w) return;

    float fx = cam[0], fy = cam[4], cx = cam[2], cy = cam[5];
    float ifx = 1.0f / fx;
    int sf = sf_ptr[0];
    int hw = h * w;
    int base = r * w + c0;

    bool interior = (r >= 1) & (r < h - 1) & (c0 >= 4) & (c0 <= w - 8);

    if (interior) {
        float4 zu4 = *(const float4*)(depth + base - w);
        float4 zd4 = *(const float4*)(depth + base + w);
        float4 zm4 = *(const float4*)(depth + base);
        float  zm0 = depth[base - 1];
        float  zm5 = depth[base + 4];

        float zu0 = zu4.x, zu1 = zu4.y, zu2 = zu4.z, zu3 = zu4.w;
        float zd0 = zd4.x, zd1 = zd4.y, zd2 = zd4.z, zd3 = zd4.w;
        float zm1 = zm4.x, zm2 = zm4.y, zm3 = zm4.z, zm4v = zm4.w;

        float fv0 = ((float)r       - cy) * ifx;
        float fvm = ((float)(r - 1) - cy) * ifx;
        float fvp = ((float)(r + 1) - cy) * ifx;

        // min-tree positivity check. fminf drops NaNs; NaN depths enter the
        // hot path where they poison exactly the affected pixel's chains ->
        // all four neighbors excluded -> nz=NaN -> fixup (0,0,-1), matching
        // the reference. Negative/zero depths still fail min>ZMIN -> generic.
        float mnU = fminf(fminf(zu0, zu1), fminf(zu2, zu3));
        float mnD = fminf(fminf(zd0, zd1), fminf(zd2, zd3));
        float mnM = fminf(fminf(fminf(zm0, zm1), fminf(zm2, zm3)), fminf(zm4v, zm5));
        bool allpos = fminf(mnU, fminf(mnD, mnM)) > ZMIN;

        if (allpos && fvp <= 0.f) {
            // Whole neighborhood masked (Y<=0 -> Z=0 -> D=inf) -> NaN cascade
            // -> reference emits exactly (0, 0, -1).
            float4 zro = make_float4(0.f, 0.f, 0.f, 0.f);
            float4 neg = make_float4(-1.f, -1.f, -1.f, -1.f);
            *(float4*)(out + base)          = zro;
            *(float4*)(out + base + hw)     = zro;
            *(float4*)(out + base + 2 * hw) = neg;
            return;
        }

        if (allpos && fvm > 0.f) {
            float fu0 = ((float)(c0 - 1) - cx) * ifx;
            float fu1 = fmaf(ifx, 1.f, fu0);
            float fu2 = fmaf(ifx, 1.f, fu1);
            float fu3 = fmaf(ifx, 1.f, fu2);
            float fu4 = fmaf(ifx, 1.f, fu3);
            float fu5 = fmaf(ifx, 1.f, fu4);

            float Dm0 = rcpa(zm0), Dm1 = rcpa(zm1), Dm2 = rcpa(zm2);
            float Dm3 = rcpa(zm3), Dm4 = rcpa(zm4v), Dm5 = rcpa(zm5);
            float Du0 = rcpa(zu0), Du1 = rcpa(zu1), Du2 = rcpa(zu2), Du3 = rcpa(zu3);
            float Dd0 = rcpa(zd0), Dd1 = rcpa(zd1), Dd2 = rcpa(zd2), Dd3 = rcpa(zd3);

            float Xm0 = zm0 * fu0, Xm1 = zm1 * fu1, Xm2 = zm2 * fu2;
            float Xm3 = zm3 * fu3, Xm4 = zm4v * fu4, Xm5 = zm5 * fu5;

            // Shared horizontal edges: E_j = (Xm_{j+1}-Xm_j) * rcp(zm_{j+1}-zm_j).
            // Pixel p's LEFT term and pixel p-1's RIGHT term are both E (the
            // right side's double negation cancels exactly; rcp.approx and
            // FMUL are sign-symmetric, so this is bit-identical to computing
            // Xd*rcp(Zd) per pixel).
            float E0 = fsub(Xm1, Xm0) * rcpa(fsub(zm1, zm0));
            float E1 = fsub(Xm2, Xm1) * rcpa(fsub(zm2, zm1));
            float E2 = fsub(Xm3, Xm2) * rcpa(fsub(zm3, zm2));
            float E3 = fsub(Xm4, Xm3) * rcpa(fsub(zm4v, zm3));
            float E4 = fsub(Xm5, Xm4) * rcpa(fsub(zm5, zm4v));

            float3 o0 = hot_pixel(zm1,  fu1, Dm0, Dm2, E0, E1,
                                  zu0, zd0, Du0, Dd0, fv0, fvm, fvp, fx, fy, sf);
            float3 o1 = hot_pixel(zm2,  fu2, Dm1, Dm3, E1, E2,
                                  zu1, zd1, Du1, Dd1, fv0, fvm, fvp, fx, fy, sf);
            float3 o2 = hot_pixel(zm3,  fu3, Dm2, Dm4, E2, E3,
                                  zu2, zd2, Du2, Dd2, fv0, fvm, fvp, fx, fy, sf);
            float3 o3 = hot_pixel(zm4v, fu4, Dm3, Dm5, E3, E4,
                                  zu3, zd3, Du3, Dd3, fv0, fvm, fvp, fx, fy, sf);

            *(float4*)(out + base)          = make_float4(o0.x, o1.x, o2.x, o3.x);
            *(float4*)(out + base + hw)     = make_float4(o0.y, o1.y, o2.y, o3.y);
            *(float4*)(out + base + 2 * hw) = make_float4(o0.z, o1.z, o2.z, o3.z);
            return;
        }
    }

    // Borders, horizon band, pathological depth values.
#pragma unroll 1
    for (int p = 0; p < 4; p++) {
        float onx, ony, onz;
        generic_pixel(depth, r, c0 + p, h, w, fx, fy, ifx, cx, cy, sf, onx, ony, onz);
        out[base + p]          = onx;
        out[base + p + hw]     = ony;
        out[base + p + 2 * hw] = onz;
    }
}

extern "C" void kernel_launch(void* const* d_in, const int* in_sizes, int n_in,
                              void* d_out, int out_size) {
    const float* depth = (const float*)d_in[0];
    const float* cam   = (const float*)d_in[1];
    const int*   sf    = (const int*)d_in[2];
    float* out = (float*)d_out;

    int w = W_IMG;
    int h = in_sizes[0] / w;

    dim3 block(32, 4);
    dim3 grid((w + 127) / 128, (h + 3) / 4);
    nim_kernel<<<grid, block>>>(depth, cam, sf, out, h, w);
}

// round 15
// speedup vs baseline: 1.0887x; 1.0307x over previous
#include <cuda_runtime.h>
#include <math.h>

#define W_IMG 4096
// float(pi) - pi  (cos(pi_f) == -1 exactly, sin(pi_f) == -DPI)
#define DPI 8.742278e-8f
#define ZMIN 1e-12f

__device__ __forceinline__ float rcpa(float x){ float y; asm("rcp.approx.f32 %0, %1;" : "=f"(y) : "f"(x)); return y; }
__device__ __forceinline__ float rsqa(float x){ float y; asm("rsqrt.approx.f32 %0, %1;" : "=f"(y) : "f"(x)); return y; }
// y with sign flipped by sign bit of x: single LOP3
__device__ __forceinline__ float xsign(float y, float x){
    return __int_as_float(__float_as_int(y) ^ (__float_as_int(x) & 0x80000000u));
}
// a - b as FFMA-imm (exact)
__device__ __forceinline__ float fsub(float a, float b){ return fmaf(b, -1.f, a); }
// float-domain ordered compares: 1.0f / 0.0f, false on NaN
__device__ __forceinline__ float fsetgt(float a, float b){
    float d; asm("set.gt.f32.f32 %0, %1, %2;" : "=f"(d) : "f"(a), "f"(b)); return d;
}
__device__ __forceinline__ float fsetne(float a, float b){
    float d; asm("set.ne.f32.f32 %0, %1, %2;" : "=f"(d) : "f"(a), "f"(b)); return d;
}

// ---------- robust sin/cos of atan(num/den): handles inf operands too -------
__device__ __forceinline__ void cs_atan_core(float num, float den, float& sa, float& ca) {
    float an = fabsf(num), ad = fabsf(den);
    bool sw = an > ad;
    float top = sw ? den : num;
    float bot = sw ? num : den;
    float q  = top * rcpa(bot);                 // |q| <= 1, or NaN
    float rr = rsqa(fmaf(q, q, 1.f));
    float sg = copysignf(1.f, num) * copysignf(1.f, den);
    ca = sw ? fabsf(q) * rr : rr;
    sa = sw ? sg * rr : q * rr;
}

// ---------- neighbor from precomputed slope term: nzn = coef*S + t ----------
__device__ __forceinline__ void neigh_s(float coef, float S, float t,
                                        float nt2, float& rn, float& v) {
    float nzn = fmaf(coef, S, t);
    rn = rsqa(fmaf(nzn, nzn, nt2));
    v  = -(nzn * rn);
}

// ---------- HOT pixel: all inputs finite positive depths (z > ZMIN) ----------
__device__ __forceinline__ float3 hot_pixel(
    float zc, float fuc,
    float DmM, float DmP,                 // 1/z left, right
    float EL, float ER,                   // shared edge ratios (dX/dH)
    float zu, float zdn, float Du, float Dd_,  // z and 1/z up, down
    float fv0, float ifx,
    float fx, float fy, int sf)
{
    float nx_t = fsub(DmP, DmM) * fx;
    float ny_t = fsub(Dd_, Du) * fy;
    float nt2 = fmaf(nx_t, nx_t, ny_t * ny_t);

    float pt   = ny_t * fv0;                  // shared by left/right
    float ptgt = fmaf(nx_t, fuc, pt);         // shared by up/down
    float nyI  = ny_t * ifx;

    // vertical slope terms:
    //   up:   Yd/Zd = fv0 + ifx * zu  / Zu    (fvm = fv0 - ifx)
    //   down: Yd/Zd = fv0 - ifx * zdn / Zdn   (fvp = fv0 + ifx)  <- NEGATIVE
    float Ru = rcpa(fsub(zc, zu));
    float Rd = rcpa(fsub(zc, zdn));
    float Su = zu  * Ru;
    float Sd = zdn * Rd;

    float rn0, v0, rn1, v1, rn2, v2, rn3, v3;
    neigh_s( nyI,  Su, ptgt, nt2, rn0, v0);   // up
    neigh_s( nx_t, EL, pt,   nt2, rn1, v1);   // left
    neigh_s( nx_t, ER, pt,   nt2, rn2, v2);   // right
    neigh_s(-nyI,  Sd, ptgt, nt2, rn3, v3);   // down (negated coefficient)

    float srn, snz;
    if (sf) {
        // signed count: sg_i = sign(v_i) as +-1.0 (0 for zero/NaN; ordered ne)
        float sg0 = xsign(fsetne(v0, 0.f), v0);
        float sg1 = xsign(fsetne(v1, 0.f), v1);
        float sg2 = xsign(fsetne(v2, 0.f), v2);
        float sg3 = xsign(fsetne(v3, 0.f), v3);
        float ssum = fmaf(sg3, 1.f, fmaf(sg2, 1.f, fmaf(sg1, 1.f, sg0)));
        // majority side = sign bit of ssum; w_i > 0 <=> kept
        float w0 = xsign(v0, ssum), w1 = xsign(v1, ssum);
        float w2 = xsign(v2, ssum), w3 = xsign(v3, ssum);
        // FMNMX absorbs NaN (fmaxf(NaN,0)=0)
        float m0 = fmaxf(w0, 0.f), m1 = fmaxf(w1, 0.f);
        float m2 = fmaxf(w2, 0.f), m3 = fmaxf(w3, 0.f);
        float msum = fmaf(m3, 1.f, fmaf(m2, 1.f, fmaf(m1, 1.f, m0)));
        snz = xsign(msum, ssum);
        float f0 = fsetgt(w0, 0.f), f1 = fsetgt(w1, 0.f);
        float f2 = fsetgt(w2, 0.f), f3 = fsetgt(w3, 0.f);
        float rc0 = fmaxf(rn0, 0.f), rc1 = fmaxf(rn1, 0.f);
        float rc2 = fmaxf(rn2, 0.f), rc3 = fmaxf(rn3, 0.f);
        srn = fmaf(f3, rc3, fmaf(f2, rc2, fmaf(f1, rc1, f0 * rc0)));
    } else {
        float cv0 = (v0 != v0) ? 0.f : v0, cr0 = (v0 != v0) ? 0.f : rn0;
        float cv1 = (v1 != v1) ? 0.f : v1, cr1 = (v1 != v1) ? 0.f : rn1;
        float cv2 = (v2 != v2) ? 0.f : v2, cr2 = (v2 != v2) ? 0.f : rn2;
        float cv3 = (v3 != v3) ? 0.f : v3, cr3 = (v3 != v3) ? 0.f : rn3;
        srn = fmaf(cr3, 1.f, fmaf(cr2, 1.f, fmaf(cr1, 1.f, cr0)));
        snz = fmaf(cv3, 1.f, fmaf(cv2, 1.f, fmaf(cv1, 1.f, cv0)));
    }

    // Collapsed reconstruction: output = sign(snz) * srn * rr * (nxr, nyr),
    // nz = |snz| * rr, where rr = rsqrt(snz^2 + srn^2*nt2). The DPI rotation
    // of the reference survives exactly in (nxr, nyr).
    float nxr = fmaf(-DPI, ny_t, nx_t);
    float nyr = fmaf(DPI, nx_t, ny_t);
    float num2 = (srn * srn) * nt2;
    float rr  = rsqa(fmaf(snz, snz, num2));
    float k   = xsign(srn * rr, snz);
    float nx = k * nxr;
    float ny = k * nyr;
    float nz = fabsf(snz) * rr;
    if (nz != nz) { nx = 0.f; ny = 0.f; nz = -1.f; }
    float s = (ny > 0.f) ? -1.f : 1.f;
    return make_float3(nx * s, ny * s, nz * s);
}

// ---------- generic finisher (robust to inf nx_t/ny_t) ----------------------
__device__ __forceinline__ void gen_finish(
    float nx_t, float ny_t,
    const float* Xd, const float* Yd, const float* Zd,
    int sf, float& onx, float& ony, float& onz)
{
    float sa, ca; cs_atan_core(ny_t, nx_t, sa, ca);
    float a = fmaf(sa, DPI, -ca);
    float b = -fmaf(ca, DPI, sa);
    float nt2 = fmaf(nx_t, nx_t, ny_t * ny_t);

    float nxv[4], nyv[4], nzv[4];
#pragma unroll
    for (int i = 0; i < 4; i++) {
        float nz_i = -fmaf(nx_t, Xd[i], ny_t * Yd[i]) * rcpa(Zd[i]);
        float rn = rsqa(fmaf(nz_i, nz_i, nt2));
        float vx = nx_t * rn, vy = ny_t * rn, vz = nz_i * rn;
        nxv[i] = (vx != vx) ? 0.f : vx;
        nyv[i] = (vy != vy) ? 0.f : vy;
        nzv[i] = (vz != vz) ? 0.f : vz;
    }
    if (sf) {
        int np = 0, nn = 0;
#pragma unroll
        for (int i = 0; i < 4; i++) { np += nzv[i] > 0.f; nn += nzv[i] < 0.f; }
        bool ps = np >= nn;
#pragma unroll
        for (int i = 0; i < 4; i++) {
            float fm = (ps ? (nzv[i] > 0.f) : (nzv[i] < 0.f)) ? 1.f : 0.f;
            nxv[i] *= fm; nyv[i] *= fm; nzv[i] *= fm;
        }
    }
    float snx = (nxv[0] + nxv[1]) + (nxv[2] + nxv[3]);
    float sny = (nyv[0] + nyv[1]) + (nyv[2] + nyv[3]);
    float snz = (nzv[0] + nzv[1]) + (nzv[2] + nzv[3]);

    float num = fmaf(snx, a, sny * b);
    float st, ct; cs_atan_core(num, snz, st, ct);
    float nx = st * a, ny = st * b, nz = ct;
    if (nz != nz) { nx = 0.f; ny = 0.f; nz = -1.f; }
    float s = (ny > 0.f) ? -1.f : 1.f;
    onx = nx * s; ony = ny * s; onz = nz * s;
}

__device__ __forceinline__ void generic_pixel(const float* __restrict__ depth,
    int r, int c, int h, int w, float fx, float fy, float ifx,
    float cx, float cy, int sf, float& onx, float& ony, float& onz)
{
    const int dy[5] = {0, -1, 0, 0, 1};
    const int dx[5] = {0,  0,-1, 1, 0};
    float Xs[5], Ys[5], Zs[5], Ds[5];
#pragma unroll
    for (int i = 0; i < 5; i++) {
        int rr_ = r + dy[i], cc = c + dx[i];
        bool inb = (rr_ >= 0) & (rr_ < h) & (cc >= 0) & (cc < w);
        float X = 0.f, Y = 0.f, Z = 0.f, D = 0.f;
        if (inb) {
            float z = depth[rr_ * w + cc];
            Z = z;
            Y = z * ((float)rr_ - cy) * ifx;   // reference uses fx for Y too
            X = z * ((float)cc - cx) * ifx;
            if (Y <= 0.f) { Z = 0.f; Y = 0.f; } // X intentionally NOT zeroed
            if (Z != Z) Z = 0.f;
            D = rcpa(Z);                         // inf where Z == 0
        }
        Xs[i] = X; Ys[i] = Y; Zs[i] = Z; Ds[i] = D;
    }
    float nx_t = (Ds[3] - Ds[2]) * fx;
    float ny_t = (Ds[4] - Ds[1]) * fy;
    float Xd[4], Yd[4], Zd[4];
#pragma unroll
    for (int i = 0; i < 4; i++) {
        Xd[i] = Xs[0] - Xs[i + 1];
        Yd[i] = Ys[0] - Ys[i + 1];
        Zd[i] = Zs[0] - Zs[i + 1];
    }
    gen_finish(nx_t, ny_t, Xd, Yd, Zd, sf, onx, ony, onz);
}

__global__ __launch_bounds__(128, 10)
void nim_kernel(const float* __restrict__ depth,
                const float* __restrict__ cam,
                const int*   __restrict__ sf_ptr,
                float* __restrict__ out,
                int h, int w)
{
    int r  = blockIdx.y * 4 + threadIdx.y;
    int c0 = (blockIdx.x * 32 + threadIdx.x) * 4;
    if (r >= h || c0 + 3 >= w) return;

    float fx = cam[0], fy = cam[4], cx = cam[2], cy = cam[5];
    float ifx = 1.0f / fx;
    int sf = sf_ptr[0];
    int hw = h * w;
    int base = r * w + c0;

    bool interior = (r >= 1) & (r < h - 1) & (c0 >= 4) & (c0 <= w - 8);

    if (interior) {
        float4 zu4 = *(const float4*)(depth + base - w);
        float4 zd4 = *(const float4*)(depth + base + w);
        float4 zm4 = *(const float4*)(depth + base);
        float  zm0 = depth[base - 1];
        float  zm5 = depth[base + 4];

        float zu0 = zu4.x, zu1 = zu4.y, zu2 = zu4.z, zu3 = zu4.w;
        float zd0 = zd4.x, zd1 = zd4.y, zd2 = zd4.z, zd3 = zd4.w;
        float zm1 = zm4.x, zm2 = zm4.y, zm3 = zm4.z, zm4v = zm4.w;

        float fv0 = ((float)r       - cy) * ifx;
        float fvm = ((float)(r - 1) - cy) * ifx;
        float fvp = ((float)(r + 1) - cy) * ifx;

        // min-tree positivity check. fminf drops NaNs; NaN depths enter the
        // hot path where they poison exactly the affected pixel's chains ->
        // all four neighbors excluded -> nz=NaN -> fixup (0,0,-1), matching
        // the reference. Negative/zero depths still fail min>ZMIN -> generic.
        float mnU = fminf(fminf(zu0, zu1), fminf(zu2, zu3));
        float mnD = fminf(fminf(zd0, zd1), fminf(zd2, zd3));
        float mnM = fminf(fminf(fminf(zm0, zm1), fminf(zm2, zm3)), fminf(zm4v, zm5));
        bool allpos = fminf(mnU, fminf(mnD, mnM)) > ZMIN;

        if (allpos && fvp <= 0.f) {
            // Whole neighborhood masked (Y<=0 -> Z=0 -> D=inf) -> NaN cascade
            // -> reference emits exactly (0, 0, -1).
            float4 zro = make_float4(0.f, 0.f, 0.f, 0.f);
            float4 neg = make_float4(-1.f, -1.f, -1.f, -1.f);
            *(float4*)(out + base)          = zro;
            *(float4*)(out + base + hw)     = zro;
            *(float4*)(out + base + 2 * hw) = neg;
            return;
        }

        if (allpos && fvm > 0.f) {
            float fu0 = ((float)(c0 - 1) - cx) * ifx;
            float fu1 = fmaf(ifx, 1.f, fu0);
            float fu2 = fmaf(ifx, 1.f, fu1);
            float fu3 = fmaf(ifx, 1.f, fu2);
            float fu4 = fmaf(ifx, 1.f, fu3);

            float Dm0 = rcpa(zm0), Dm1 = rcpa(zm1), Dm2 = rcpa(zm2);
            float Dm3 = rcpa(zm3), Dm4 = rcpa(zm4v), Dm5 = rcpa(zm5);
            float Du0 = rcpa(zu0), Du1 = rcpa(zu1), Du2 = rcpa(zu2), Du3 = rcpa(zu3);
            float Dd0 = rcpa(zd0), Dd1 = rcpa(zd1), Dd2 = rcpa(zd2), Dd3 = rcpa(zd3);

            // Shared horizontal edges, ladder form:
            // E_j = dX/dH ~= fu_j + ifx * zm_{j+1} / dH  (dX expanded through
            // the fu ladder). Pixel p's LEFT and pixel p-1's RIGHT share E.
            // dH=0 -> E=+-inf/NaN -> neighbor dropped, as in the reference.
            float E0 = fmaf(zm1  * ifx, rcpa(fsub(zm1,  zm0)),  fu0);
            float E1 = fmaf(zm2  * ifx, rcpa(fsub(zm2,  zm1)),  fu1);
            float E2 = fmaf(zm3  * ifx, rcpa(fsub(zm3,  zm2)),  fu2);
            float E3 = fmaf(zm4v * ifx, rcpa(fsub(zm4v, zm3)),  fu3);
            float E4 = fmaf(zm5  * ifx, rcpa(fsub(zm5,  zm4v)), fu4);

            float3 o0 = hot_pixel(zm1,  fu1, Dm0, Dm2, E0, E1,
                                  zu0, zd0, Du0, Dd0, fv0, ifx, fx, fy, sf);
            float3 o1 = hot_pixel(zm2,  fu2, Dm1, Dm3, E1, E2,
                                  zu1, zd1, Du1, Dd1, fv0, ifx, fx, fy, sf);
            float3 o2 = hot_pixel(zm3,  fu3, Dm2, Dm4, E2, E3,
                                  zu2, zd2, Du2, Dd2, fv0, ifx, fx, fy, sf);
            float3 o3 = hot_pixel(zm4v, fu4, Dm3, Dm5, E3, E4,
                                  zu3, zd3, Du3, Dd3, fv0, ifx, fx, fy, sf);

            *(float4*)(out + base)          = make_float4(o0.x, o1.x, o2.x, o3.x);
            *(float4*)(out + base + hw)     = make_float4(o0.y, o1.y, o2.y, o3.y);
            *(float4*)(out + base + 2 * hw) = make_float4(o0.z, o1.z, o2.z, o3.z);
            return;
        }
    }

    // Borders, horizon band, pathological depth values.
#pragma unroll 1
    for (int p = 0; p < 4; p++) {
        float onx, ony, onz;
        generic_pixel(depth, r, c0 + p, h, w, fx, fy, ifx, cx, cy, sf, onx, ony, onz);
        out[base + p]          = onx;
        out[base + p + hw]     = ony;
        out[base + p + 2 * hw] = onz;
    }
}

extern "C" void kernel_launch(void* const* d_in, const int* in_sizes, int n_in,
                              void* d_out, int out_size) {
    const float* depth = (const float*)d_in[0];
    const float* cam   = (const float*)d_in[1];
    const int*   sf    = (const int*)d_in[2];
    float* out = (float*)d_out;

    int w = W_IMG;
    int h = in_sizes[0] / w;

    dim3 block(32, 4);
    dim3 grid((w + 127) / 128, (h + 3) / 4);
    nim_kernel<<<grid, block>>>(depth, cam, sf, out, h, w);
}